// round 1
// baseline (speedup 1.0000x reference)
#include <cuda_runtime.h>

// Problem dims
constexpr int B_ = 16, S_ = 4096, D_ = 512, M_ = 2048;
constexpr int NROWS = B_ * S_;   // 65536
constexpr int KD    = D_;        // 512
constexpr int NC    = 3 * D_;    // 1536

// Scratch (device globals: no allocations allowed in kernel_launch)
__device__ float g_v[(size_t)NROWS * D_];      // v projection (134 MB)
__device__ float g_scores[NROWS];
__device__ float g_attn[NROWS];
__device__ float g_part[B_ * 16 * D_];
__device__ float g_h[B_ * D_];
__device__ float g_h1[B_ * M_];
__device__ float g_h2[B_ * M_];

// ---------------------------------------------------------------------------
// QKV GEMM:  C[65536 x 1536] = x[65536 x 512] @ W_qkv[512 x 1536] + b_qkv
// Tile 128x128x16, 256 threads, 8x8 register blocking, double-buffered smem.
// Column region is constant per block (BN=128 divides 512): 0..3 -> q,
// 4..7 -> k, 8..11 -> v.
// ---------------------------------------------------------------------------
constexpr int BM = 128, BN = 128, BK = 16;

__global__ __launch_bounds__(256, 2)
void qkv_gemm(const float* __restrict__ A, const float* __restrict__ W,
              const float* __restrict__ bias,
              float* __restrict__ q_out, float* __restrict__ k_out)
{
    __shared__ float As[2][BK][BM];   // transposed: [k][m]
    __shared__ float Bs[2][BK][BN];   // [k][n]

    const int tid = threadIdx.x;
    const int m0 = blockIdx.y * BM;
    const int n0 = blockIdx.x * BN;

    const int ty = tid >> 4;   // 0..15 -> row group (8 rows)
    const int tx = tid & 15;   // 0..15 -> col group (8 cols)

    // Loader coordinates (2 float4 each from A and W per thread)
    const int ar0 = tid >> 2;                const int ak0 = (tid & 3) * 4;
    const int ar1 = (tid + 256) >> 2;        const int ak1 = ((tid + 256) & 3) * 4;
    const int bk0 = tid >> 5;                const int bn0 = (tid & 31) * 4;
    const int bk1 = (tid + 256) >> 5;        const int bn1 = ((tid + 256) & 31) * 4;

    const float* Abase = A + (size_t)m0 * KD;
    const float* Wbase = W + n0;

    float4 a0r, a1r, b0r, b1r;

    // preload tile 0
    a0r = *(const float4*)(Abase + (size_t)ar0 * KD + ak0);
    a1r = *(const float4*)(Abase + (size_t)ar1 * KD + ak1);
    b0r = *(const float4*)(Wbase + (size_t)bk0 * NC + bn0);
    b1r = *(const float4*)(Wbase + (size_t)bk1 * NC + bn1);

    As[0][ak0+0][ar0] = a0r.x; As[0][ak0+1][ar0] = a0r.y;
    As[0][ak0+2][ar0] = a0r.z; As[0][ak0+3][ar0] = a0r.w;
    As[0][ak1+0][ar1] = a1r.x; As[0][ak1+1][ar1] = a1r.y;
    As[0][ak1+2][ar1] = a1r.z; As[0][ak1+3][ar1] = a1r.w;
    *(float4*)&Bs[0][bk0][bn0] = b0r;
    *(float4*)&Bs[0][bk1][bn1] = b1r;
    __syncthreads();

    float acc[8][8];
    #pragma unroll
    for (int i = 0; i < 8; i++)
        #pragma unroll
        for (int j = 0; j < 8; j++) acc[i][j] = 0.f;

    int buf = 0;
    constexpr int NT = KD / BK;   // 32
    for (int t = 0; t < NT; t++) {
        if (t + 1 < NT) {
            const int kt = (t + 1) * BK;
            a0r = *(const float4*)(Abase + (size_t)ar0 * KD + kt + ak0);
            a1r = *(const float4*)(Abase + (size_t)ar1 * KD + kt + ak1);
            b0r = *(const float4*)(Wbase + (size_t)(kt + bk0) * NC + bn0);
            b1r = *(const float4*)(Wbase + (size_t)(kt + bk1) * NC + bn1);
        }
        #pragma unroll
        for (int kk = 0; kk < BK; kk++) {
            float4 av0 = *(const float4*)&As[buf][kk][ty * 8];
            float4 av1 = *(const float4*)&As[buf][kk][ty * 8 + 4];
            float4 bv0 = *(const float4*)&Bs[buf][kk][tx * 8];
            float4 bv1 = *(const float4*)&Bs[buf][kk][tx * 8 + 4];
            float a[8] = {av0.x, av0.y, av0.z, av0.w, av1.x, av1.y, av1.z, av1.w};
            float b[8] = {bv0.x, bv0.y, bv0.z, bv0.w, bv1.x, bv1.y, bv1.z, bv1.w};
            #pragma unroll
            for (int i = 0; i < 8; i++)
                #pragma unroll
                for (int j = 0; j < 8; j++)
                    acc[i][j] = fmaf(a[i], b[j], acc[i][j]);
        }
        if (t + 1 < NT) {
            const int nb = buf ^ 1;
            As[nb][ak0+0][ar0] = a0r.x; As[nb][ak0+1][ar0] = a0r.y;
            As[nb][ak0+2][ar0] = a0r.z; As[nb][ak0+3][ar0] = a0r.w;
            As[nb][ak1+0][ar1] = a1r.x; As[nb][ak1+1][ar1] = a1r.y;
            As[nb][ak1+2][ar1] = a1r.z; As[nb][ak1+3][ar1] = a1r.w;
            *(float4*)&Bs[nb][bk0][bn0] = b0r;
            *(float4*)&Bs[nb][bk1][bn1] = b1r;
            __syncthreads();
            buf = nb;
        }
    }

    // Epilogue: add bias, route to q / k / v
    const int region = n0 >> 9;          // 0=q, 1=k, 2=v
    float* dst = (region == 0) ? q_out : (region == 1 ? k_out : (float*)g_v);
    const int gn0 = n0 + tx * 8;         // global col of first output
    const int lc0 = gn0 - region * 512;  // col within region

    float bsv[8];
    #pragma unroll
    for (int j = 0; j < 8; j++) bsv[j] = bias[gn0 + j];

    #pragma unroll
    for (int i = 0; i < 8; i++) {
        const size_t r = (size_t)(m0 + ty * 8 + i);
        float4 o0 = make_float4(acc[i][0] + bsv[0], acc[i][1] + bsv[1],
                                acc[i][2] + bsv[2], acc[i][3] + bsv[3]);
        float4 o1 = make_float4(acc[i][4] + bsv[4], acc[i][5] + bsv[5],
                                acc[i][6] + bsv[6], acc[i][7] + bsv[7]);
        *(float4*)(dst + r * D_ + lc0)     = o0;
        *(float4*)(dst + r * D_ + lc0 + 4) = o1;
    }
}

// ---------------------------------------------------------------------------
// scores[b,s] = q_last[b,:] . k[b,s,:]    (one warp per (b,s))
// ---------------------------------------------------------------------------
__global__ void scores_kernel(const float* __restrict__ q, const float* __restrict__ k)
{
    const int gw   = (blockIdx.x * blockDim.x + threadIdx.x) >> 5;
    const int lane = threadIdx.x & 31;
    const int b    = gw >> 12;   // / 4096

    const float4* qr = (const float4*)(q + ((size_t)b * S_ + (S_ - 1)) * D_);
    const float4* kr = (const float4*)(k + (size_t)gw * D_);

    float acc = 0.f;
    #pragma unroll
    for (int it = 0; it < 4; it++) {
        float4 qv = qr[lane + it * 32];
        float4 kv = kr[lane + it * 32];
        acc += qv.x * kv.x + qv.y * kv.y + qv.z * kv.z + qv.w * kv.w;
    }
    #pragma unroll
    for (int off = 16; off; off >>= 1) acc += __shfl_xor_sync(0xffffffffu, acc, off);
    if (lane == 0) g_scores[gw] = acc;
}

// ---------------------------------------------------------------------------
// softmax over S per batch
// ---------------------------------------------------------------------------
__global__ void softmax_kernel()
{
    __shared__ float red[512];
    const int b = blockIdx.x, tid = threadIdx.x;
    const float* sc = g_scores + (size_t)b * S_;

    float lm = -1e30f;
    for (int i = tid; i < S_; i += 512) lm = fmaxf(lm, sc[i]);
    red[tid] = lm; __syncthreads();
    for (int s = 256; s; s >>= 1) {
        if (tid < s) red[tid] = fmaxf(red[tid], red[tid + s]);
        __syncthreads();
    }
    const float mx = red[0];
    __syncthreads();

    float ls = 0.f;
    for (int i = tid; i < S_; i += 512) {
        float e = expf(sc[i] - mx);
        g_attn[(size_t)b * S_ + i] = e;
        ls += e;
    }
    red[tid] = ls; __syncthreads();
    for (int s = 256; s; s >>= 1) {
        if (tid < s) red[tid] += red[tid + s];
        __syncthreads();
    }
    const float inv = 1.f / red[0];
    for (int i = tid; i < S_; i += 512) g_attn[(size_t)b * S_ + i] *= inv;
}

// ---------------------------------------------------------------------------
// sa_last partial sums: block (b, chunk) accumulates 256 s-rows of attn*v
// ---------------------------------------------------------------------------
__global__ void sa_part_kernel()
{
    const int b = blockIdx.x, ch = blockIdx.y, d = threadIdx.x;
    const float* vp = g_v + ((size_t)b * S_ + ch * 256) * D_ + d;
    const float* ap = g_attn + (size_t)b * S_ + ch * 256;
    float acc = 0.f;
    #pragma unroll 4
    for (int s = 0; s < 256; s++) acc = fmaf(ap[s], vp[(size_t)s * D_], acc);
    g_part[(b * 16 + ch) * D_ + d] = acc;
}

// h[b,d] = x[b, S-1, d] + sum_ch part[b,ch,d]
__global__ void sa_reduce_kernel(const float* __restrict__ x)
{
    const int b = blockIdx.x, d = threadIdx.x;
    float acc = x[((size_t)b * S_ + (S_ - 1)) * D_ + d];
    #pragma unroll
    for (int ch = 0; ch < 16; ch++) acc += g_part[(b * 16 + ch) * D_ + d];
    g_h[b * D_ + d] = acc;
}

// ---------------------------------------------------------------------------
// MLP layers
// ---------------------------------------------------------------------------
__global__ __launch_bounds__(256)
void mlp1_kernel(const float* __restrict__ W1, const float* __restrict__ b1)
{
    __shared__ float hs[D_];
    const int b = blockIdx.x, tid = threadIdx.x;
    hs[tid]       = g_h[b * D_ + tid];
    hs[tid + 256] = g_h[b * D_ + tid + 256];
    __syncthreads();
    const int m = blockIdx.y * 256 + tid;
    float acc = b1[m];
    #pragma unroll 8
    for (int k = 0; k < D_; k++) acc = fmaf(hs[k], W1[(size_t)k * M_ + m], acc);
    g_h1[b * M_ + m] = fmaxf(acc, 0.f);
}

__global__ __launch_bounds__(256)
void mlp2_kernel(const float* __restrict__ W2, const float* __restrict__ b2)
{
    __shared__ float hs[M_];
    const int b = blockIdx.x, tid = threadIdx.x;
    for (int i = tid; i < M_; i += 256) hs[i] = g_h1[b * M_ + i];
    __syncthreads();
    const int m = blockIdx.y * 256 + tid;
    float acc = b2[m];
    #pragma unroll 8
    for (int k = 0; k < M_; k++) acc = fmaf(hs[k], W2[(size_t)k * M_ + m], acc);
    g_h2[b * M_ + m] = fmaxf(acc, 0.f);
}

__global__ void mlp3_kernel(const float* __restrict__ W3, const float* __restrict__ b3,
                            float* __restrict__ out)
{
    const int w = threadIdx.x >> 5, lane = threadIdx.x & 31;  // warp = batch
    float acc = 0.f;
    #pragma unroll
    for (int i = 0; i < M_ / 32; i++)
        acc = fmaf(g_h2[w * M_ + lane + i * 32], W3[lane + i * 32], acc);
    #pragma unroll
    for (int off = 16; off; off >>= 1) acc += __shfl_xor_sync(0xffffffffu, acc, off);
    if (lane == 0) out[w] = acc + b3[0];
}

// ---------------------------------------------------------------------------
// Entry point. Output layout assumption: tuple (out, q, k) concatenated flat:
//   [0,16)                      out  (B,1)
//   [16, 16+B*S*D)              q    (B,S,D)
//   [16+B*S*D, 16+2*B*S*D)      k    (B,S,D)
// ---------------------------------------------------------------------------
extern "C" void kernel_launch(void* const* d_in, const int* in_sizes, int n_in,
                              void* d_out, int out_size)
{
    const float* x     = (const float*)d_in[0];
    const float* W_qkv = (const float*)d_in[1];
    const float* b_qkv = (const float*)d_in[2];
    const float* W1    = (const float*)d_in[3];
    const float* b1    = (const float*)d_in[4];
    const float* W2    = (const float*)d_in[5];
    const float* b2    = (const float*)d_in[6];
    const float* W3    = (const float*)d_in[7];
    const float* b3    = (const float*)d_in[8];

    float* out   = (float*)d_out;
    float* q_out = out + 16;
    float* k_out = out + 16 + (size_t)NROWS * D_;

    qkv_gemm<<<dim3(NC / BN, NROWS / BM), 256>>>(x, W_qkv, b_qkv, q_out, k_out);
    scores_kernel<<<NROWS / 8, 256>>>(q_out, k_out);
    softmax_kernel<<<B_, 512>>>();
    sa_part_kernel<<<dim3(B_, 16), 512>>>();
    sa_reduce_kernel<<<B_, D_>>>(x);
    mlp1_kernel<<<dim3(B_, M_ / 256), 256>>>(W1, b1);
    mlp2_kernel<<<dim3(B_, M_ / 256), 256>>>(W2, b2);
    mlp3_kernel<<<1, 512>>>(W3, b3, out);
}

// round 3
// speedup vs baseline: 2.1742x; 2.1742x over previous
#include <cuda_runtime.h>
#include <cuda_bf16.h>
#include <cstdint>

// Problem dims
constexpr int B_ = 16, S_ = 4096, D_ = 512, M_ = 2048;
constexpr int NROWS = B_ * S_;   // 65536
constexpr int NC    = 3 * D_;    // 1536

// ---------------------------------------------------------------------------
// Scratch (device globals: no allocations allowed)
// ---------------------------------------------------------------------------
__device__ float g_v[(size_t)NROWS * D_];                 // v projection
__device__ __nv_bfloat16 g_xh[(size_t)NROWS * D_];        // x hi split
__device__ __nv_bfloat16 g_xl[(size_t)NROWS * D_];        // x lo split
__device__ __nv_bfloat16 g_wh[(size_t)NC * D_];           // W^T hi  [n][k]
__device__ __nv_bfloat16 g_wl[(size_t)NC * D_];           // W^T lo  [n][k]
__device__ float g_scores[NROWS];
__device__ float g_attn[NROWS];
__device__ float g_part[B_ * 16 * D_];
__device__ float g_h[B_ * D_];
__device__ float g_h1[B_ * M_];
__device__ float g_h2[B_ * M_];

// ---------------------------------------------------------------------------
// Helpers (baseline PTX only: ldmatrix / mma.sync / cp.async — all sm_80+)
// ---------------------------------------------------------------------------
__device__ __forceinline__ uint32_t smem_u32(const void* p) {
    uint32_t a;
    asm("{ .reg .u64 t; cvta.to.shared.u64 t, %1; cvt.u32.u64 %0, t; }"
        : "=r"(a) : "l"(p));
    return a;
}

// Swizzle<1,4,3> for 32-byte rows: bit4 ^= bit7 (conflict-free 8-row ldmatrix)
#define SWZ32(o) ((o) ^ ((((uint32_t)(o)) >> 3) & 0x10u))

__device__ __forceinline__ void cp_async16(uint32_t sdst, const void* gsrc) {
    asm volatile("cp.async.cg.shared.global [%0], [%1], 16;"
                 :: "r"(sdst), "l"(gsrc) : "memory");
}
#define CP_COMMIT() asm volatile("cp.async.commit_group;" ::: "memory")
#define CP_WAIT(n)  asm volatile("cp.async.wait_group %0;" :: "n"(n) : "memory")

__device__ __forceinline__ void ldm_x4(uint32_t* r, uint32_t addr) {
    asm volatile("ldmatrix.sync.aligned.m8n8.x4.shared.b16 {%0,%1,%2,%3}, [%4];"
                 : "=r"(r[0]), "=r"(r[1]), "=r"(r[2]), "=r"(r[3]) : "r"(addr));
}

__device__ __forceinline__ void mma_bf16(float* c, const uint32_t* a, const uint32_t* b) {
    asm volatile(
        "mma.sync.aligned.m16n8k16.row.col.f32.bf16.bf16.f32 "
        "{%0,%1,%2,%3}, {%4,%5,%6,%7}, {%8,%9}, {%0,%1,%2,%3};"
        : "+f"(c[0]), "+f"(c[1]), "+f"(c[2]), "+f"(c[3])
        : "r"(a[0]), "r"(a[1]), "r"(a[2]), "r"(a[3]), "r"(b[0]), "r"(b[1]));
}

// ---------------------------------------------------------------------------
// fp32 -> bf16 hi/lo split conversions
// ---------------------------------------------------------------------------
__global__ void convert_x(const float* __restrict__ x)
{
    const size_t i = (size_t)blockIdx.x * blockDim.x + threadIdx.x;  // float4 idx
    const float4 v = ((const float4*)x)[i];
    __nv_bfloat16 h0 = __float2bfloat16(v.x), h1 = __float2bfloat16(v.y);
    __nv_bfloat16 h2 = __float2bfloat16(v.z), h3 = __float2bfloat16(v.w);
    __nv_bfloat16 l0 = __float2bfloat16(v.x - __bfloat162float(h0));
    __nv_bfloat16 l1 = __float2bfloat16(v.y - __bfloat162float(h1));
    __nv_bfloat16 l2 = __float2bfloat16(v.z - __bfloat162float(h2));
    __nv_bfloat16 l3 = __float2bfloat16(v.w - __bfloat162float(h3));
    ((__nv_bfloat162*)g_xh)[i * 2 + 0] = __halves2bfloat162(h0, h1);
    ((__nv_bfloat162*)g_xh)[i * 2 + 1] = __halves2bfloat162(h2, h3);
    ((__nv_bfloat162*)g_xl)[i * 2 + 0] = __halves2bfloat162(l0, l1);
    ((__nv_bfloat162*)g_xl)[i * 2 + 1] = __halves2bfloat162(l2, l3);
}

__global__ void convert_w(const float* __restrict__ W)
{
    const int e = blockIdx.x * blockDim.x + threadIdx.x;   // < 512*1536
    const int k = e / NC, n = e % NC;
    const float v = W[e];
    __nv_bfloat16 hi = __float2bfloat16(v);
    __nv_bfloat16 lo = __float2bfloat16(v - __bfloat162float(hi));
    g_wh[(size_t)n * D_ + k] = hi;
    g_wl[(size_t)n * D_ + k] = lo;
}

// ---------------------------------------------------------------------------
// QKV GEMM via mma.sync bf16x3:
//   C[65536 x 1536] = x[65536 x 512] @ W[512 x 1536] + b
// CTA tile 128x128, K-chunk 16, cp.async double-buffered.
// 8 warps: warp_m = warp&1 (x64 rows), warp_n = warp>>1 (x32 cols).
// Per k-step: 16 frag-mmas x 3 passes (Ah*Bh, Ah*Bl, Al*Bh).
// ---------------------------------------------------------------------------
constexpr int TM = 128, TN = 128, TK = 16;
constexpr int NCHUNK = D_ / TK;  // 32
// smem: 2 stages x 4 tiles (Ah, Al, Bh, Bl) x 4KB (128 rows x 32B)
constexpr int STAGE_BYTES = 4 * 4096;

__global__ __launch_bounds__(256)
void qkv_mma(const float* __restrict__ bias,
             float* __restrict__ q_out, float* __restrict__ k_out)
{
    __shared__ __align__(128) uint8_t sm[2 * STAGE_BYTES];   // 32 KB
    const uint32_t sb = smem_u32(sm);

    const int tid  = threadIdx.x;
    const int warp = tid >> 5, lane = tid & 31;
    const int n0 = blockIdx.x * TN;
    const int m0 = blockIdx.y * TM;
    const int wm = (warp & 1) * 64;        // warp row offset
    const int wn = (warp >> 1) * 32;       // warp col offset

    // per-thread cp.async coords: one 16B chunk per tile (128 rows x 2 cols)
    const int lr = tid >> 1;               // row 0..127
    const int lc = tid & 1;                // 16B col 0..1
    const uint32_t so = SWZ32(lr * 32 + lc * 16);

    const __nv_bfloat16* xh = g_xh;
    const __nv_bfloat16* xl = g_xl;
    const __nv_bfloat16* wh = g_wh;
    const __nv_bfloat16* wl = g_wl;

    auto load_stage = [&](int stage, int ch) {
        const size_t ga = (size_t)(m0 + lr) * D_ + ch * TK + lc * 8;
        const size_t gb = (size_t)(n0 + lr) * D_ + ch * TK + lc * 8;
        const uint32_t s0 = sb + stage * STAGE_BYTES;
        cp_async16(s0 + 0 * 4096 + so, xh + ga);
        cp_async16(s0 + 1 * 4096 + so, xl + ga);
        cp_async16(s0 + 2 * 4096 + so, wh + gb);
        cp_async16(s0 + 3 * 4096 + so, wl + gb);
    };

    float acc[4][4][4];
    #pragma unroll
    for (int i = 0; i < 4; i++)
        #pragma unroll
        for (int j = 0; j < 4; j++)
            #pragma unroll
            for (int e = 0; e < 4; e++) acc[i][j][e] = 0.f;

    // ldmatrix lane addressing (within a 128x16 bf16 tile, 32B rows, SWZ32)
    // A frags (m16k16 x4): row = wm + mf*16 + (lane&15), byte = (lane>>4)*16
    const uint32_t a_off = SWZ32((uint32_t)(wm + (lane & 15)) * 32 + ((lane >> 4) << 4));
    // B frags (two n-frags per x4): row = wn + p*16 + ((lane>>4)<<3) + (lane&7),
    //                               byte = ((lane>>3)&1)*16
    const uint32_t b_row = wn + ((lane >> 4) << 3) + (lane & 7);
    const uint32_t b_off = SWZ32(b_row * 32 + (((lane >> 3) & 1) << 4));

    load_stage(0, 0);
    CP_COMMIT();

    for (int ch = 0; ch < NCHUNK; ch++) {
        if (ch + 1 < NCHUNK) { load_stage((ch + 1) & 1, ch + 1); CP_COMMIT(); }
        if (ch + 1 < NCHUNK) { CP_WAIT(1); } else { CP_WAIT(0); }
        __syncthreads();

        const uint32_t s0 = sb + (ch & 1) * STAGE_BYTES;
        uint32_t ah[4][4], al[4][4], bh[4][2], bl[4][2];
        #pragma unroll
        for (int mf = 0; mf < 4; mf++) {
            ldm_x4(ah[mf], s0 + 0 * 4096 + a_off + SWZ32(mf * 16 * 32) - SWZ32(0) + (a_off ^ a_off));
        }
        // NOTE: swizzle is not additive; compute addresses directly instead.
        #pragma unroll
        for (int mf = 0; mf < 4; mf++) {
            const uint32_t ra = SWZ32((uint32_t)(wm + mf * 16 + (lane & 15)) * 32 + ((lane >> 4) << 4));
            ldm_x4(ah[mf], s0 + 0 * 4096 + ra);
            ldm_x4(al[mf], s0 + 1 * 4096 + ra);
        }
        #pragma unroll
        for (int p = 0; p < 2; p++) {
            const uint32_t rb = SWZ32((uint32_t)(wn + p * 16 + ((lane >> 4) << 3) + (lane & 7)) * 32
                                      + (((lane >> 3) & 1) << 4));
            uint32_t t[4];
            ldm_x4(t, s0 + 2 * 4096 + rb);
            bh[p * 2][0] = t[0]; bh[p * 2][1] = t[1];
            bh[p * 2 + 1][0] = t[2]; bh[p * 2 + 1][1] = t[3];
            ldm_x4(t, s0 + 3 * 4096 + rb);
            bl[p * 2][0] = t[0]; bl[p * 2][1] = t[1];
            bl[p * 2 + 1][0] = t[2]; bl[p * 2 + 1][1] = t[3];
        }

        #pragma unroll
        for (int mf = 0; mf < 4; mf++)
            #pragma unroll
            for (int nf = 0; nf < 4; nf++) {
                mma_bf16(acc[mf][nf], ah[mf], bh[nf]);
                mma_bf16(acc[mf][nf], ah[mf], bl[nf]);
                mma_bf16(acc[mf][nf], al[mf], bh[nf]);
            }
        __syncthreads();
    }

    // Epilogue: direct global float2 stores (+bias), route q/k/v per CTA
    const int region = n0 >> 9;                 // 0=q, 1=k, 2=v
    float* dst = (region == 0) ? q_out : (region == 1 ? k_out : (float*)g_v);
    const int cbase = n0 - region * 512;

    #pragma unroll
    for (int mf = 0; mf < 4; mf++) {
        #pragma unroll
        for (int nf = 0; nf < 4; nf++) {
            const int colg = n0 + wn + nf * 8 + (lane & 3) * 2;
            const float2 bv = *(const float2*)(bias + colg);
            const int col = cbase + wn + nf * 8 + (lane & 3) * 2;
            const int r0 = m0 + wm + mf * 16 + (lane >> 2);
            float2 v0 = make_float2(acc[mf][nf][0] + bv.x, acc[mf][nf][1] + bv.y);
            float2 v1 = make_float2(acc[mf][nf][2] + bv.x, acc[mf][nf][3] + bv.y);
            *(float2*)(dst + (size_t)r0 * D_ + col)       = v0;
            *(float2*)(dst + (size_t)(r0 + 8) * D_ + col) = v1;
        }
    }
}

// ---------------------------------------------------------------------------
// scores[b,s] = q_last[b,:] . k[b,s,:]    (one warp per (b,s))
// ---------------------------------------------------------------------------
__global__ void scores_kernel(const float* __restrict__ q, const float* __restrict__ k)
{
    const int gw   = (blockIdx.x * blockDim.x + threadIdx.x) >> 5;
    const int lane = threadIdx.x & 31;
    const int b    = gw >> 12;

    const float4* qr = (const float4*)(q + ((size_t)b * S_ + (S_ - 1)) * D_);
    const float4* kr = (const float4*)(k + (size_t)gw * D_);

    float acc = 0.f;
    #pragma unroll
    for (int it = 0; it < 4; it++) {
        float4 qv = qr[lane + it * 32];
        float4 kv = kr[lane + it * 32];
        acc += qv.x * kv.x + qv.y * kv.y + qv.z * kv.z + qv.w * kv.w;
    }
    #pragma unroll
    for (int off = 16; off; off >>= 1) acc += __shfl_xor_sync(0xffffffffu, acc, off);
    if (lane == 0) g_scores[gw] = acc;
}

__global__ void softmax_kernel()
{
    __shared__ float red[512];
    const int b = blockIdx.x, tid = threadIdx.x;
    const float* sc = g_scores + (size_t)b * S_;

    float lm = -1e30f;
    for (int i = tid; i < S_; i += 512) lm = fmaxf(lm, sc[i]);
    red[tid] = lm; __syncthreads();
    for (int s = 256; s; s >>= 1) {
        if (tid < s) red[tid] = fmaxf(red[tid], red[tid + s]);
        __syncthreads();
    }
    const float mx = red[0];
    __syncthreads();

    float ls = 0.f;
    for (int i = tid; i < S_; i += 512) {
        float e = expf(sc[i] - mx);
        g_attn[(size_t)b * S_ + i] = e;
        ls += e;
    }
    red[tid] = ls; __syncthreads();
    for (int s = 256; s; s >>= 1) {
        if (tid < s) red[tid] += red[tid + s];
        __syncthreads();
    }
    const float inv = 1.f / red[0];
    for (int i = tid; i < S_; i += 512) g_attn[(size_t)b * S_ + i] *= inv;
}

__global__ void sa_part_kernel()
{
    const int b = blockIdx.x, ch = blockIdx.y, d = threadIdx.x;
    const float* vp = g_v + ((size_t)b * S_ + ch * 256) * D_ + d;
    const float* ap = g_attn + (size_t)b * S_ + ch * 256;
    float acc = 0.f;
    #pragma unroll 4
    for (int s = 0; s < 256; s++) acc = fmaf(ap[s], vp[(size_t)s * D_], acc);
    g_part[(b * 16 + ch) * D_ + d] = acc;
}

__global__ void sa_reduce_kernel(const float* __restrict__ x)
{
    const int b = blockIdx.x, d = threadIdx.x;
    float acc = x[((size_t)b * S_ + (S_ - 1)) * D_ + d];
    #pragma unroll
    for (int ch = 0; ch < 16; ch++) acc += g_part[(b * 16 + ch) * D_ + d];
    g_h[b * D_ + d] = acc;
}

__global__ __launch_bounds__(256)
void mlp1_kernel(const float* __restrict__ W1, const float* __restrict__ b1)
{
    __shared__ float hs[D_];
    const int b = blockIdx.x, tid = threadIdx.x;
    hs[tid]       = g_h[b * D_ + tid];
    hs[tid + 256] = g_h[b * D_ + tid + 256];
    __syncthreads();
    const int m = blockIdx.y * 256 + tid;
    float acc = b1[m];
    #pragma unroll 8
    for (int k = 0; k < D_; k++) acc = fmaf(hs[k], W1[(size_t)k * M_ + m], acc);
    g_h1[b * M_ + m] = fmaxf(acc, 0.f);
}

__global__ __launch_bounds__(256)
void mlp2_kernel(const float* __restrict__ W2, const float* __restrict__ b2)
{
    __shared__ float hs[M_];
    const int b = blockIdx.x, tid = threadIdx.x;
    for (int i = tid; i < M_; i += 256) hs[i] = g_h1[b * M_ + i];
    __syncthreads();
    const int m = blockIdx.y * 256 + tid;
    float acc = b2[m];
    #pragma unroll 8
    for (int k = 0; k < M_; k++) acc = fmaf(hs[k], W2[(size_t)k * M_ + m], acc);
    g_h2[b * M_ + m] = fmaxf(acc, 0.f);
}

__global__ void mlp3_kernel(const float* __restrict__ W3, const float* __restrict__ b3,
                            float* __restrict__ out)
{
    const int w = threadIdx.x >> 5, lane = threadIdx.x & 31;
    float acc = 0.f;
    #pragma unroll
    for (int i = 0; i < M_ / 32; i++)
        acc = fmaf(g_h2[w * M_ + lane + i * 32], W3[lane + i * 32], acc);
    #pragma unroll
    for (int off = 16; off; off >>= 1) acc += __shfl_xor_sync(0xffffffffu, acc, off);
    if (lane == 0) out[w] = acc + b3[0];
}

// ---------------------------------------------------------------------------
// Entry. Output layout: (out, q, k) flat: [0,16) out, then q, then k.
// ---------------------------------------------------------------------------
extern "C" void kernel_launch(void* const* d_in, const int* in_sizes, int n_in,
                              void* d_out, int out_size)
{
    const float* x     = (const float*)d_in[0];
    const float* W_qkv = (const float*)d_in[1];
    const float* b_qkv = (const float*)d_in[2];
    const float* W1    = (const float*)d_in[3];
    const float* b1    = (const float*)d_in[4];
    const float* W2    = (const float*)d_in[5];
    const float* b2    = (const float*)d_in[6];
    const float* W3    = (const float*)d_in[7];
    const float* b3    = (const float*)d_in[8];

    float* out   = (float*)d_out;
    float* q_out = out + 16;
    float* k_out = out + 16 + (size_t)NROWS * D_;

    convert_x<<<(NROWS * D_ / 4) / 256, 256>>>(x);
    convert_w<<<(D_ * NC) / 256, 256>>>(W_qkv);
    qkv_mma<<<dim3(NC / TN, NROWS / TM), 256>>>(b_qkv, q_out, k_out);
    scores_kernel<<<NROWS / 8, 256>>>(q_out, k_out);
    softmax_kernel<<<B_, 512>>>();
    sa_part_kernel<<<dim3(B_, 16), 512>>>();
    sa_reduce_kernel<<<B_, D_>>>(x);
    mlp1_kernel<<<dim3(B_, M_ / 256), 256>>>(W1, b1);
    mlp2_kernel<<<dim3(B_, M_ / 256), 256>>>(W2, b2);
    mlp3_kernel<<<1, 512>>>(W3, b3, out);
}

// round 4
// speedup vs baseline: 2.1809x; 1.0031x over previous
#include <cuda_runtime.h>
#include <cuda_bf16.h>
#include <cstdint>

// Problem dims
constexpr int B_ = 16, S_ = 4096, D_ = 512, M_ = 2048;
constexpr int NROWS = B_ * S_;   // 65536
constexpr int NC    = 3 * D_;    // 1536

// ---------------------------------------------------------------------------
// Scratch (device globals: no allocations allowed)
// ---------------------------------------------------------------------------
__device__ float g_v[(size_t)NROWS * D_];                 // v projection
__device__ __nv_bfloat16 g_xh[(size_t)NROWS * D_];        // x hi split
__device__ __nv_bfloat16 g_xl[(size_t)NROWS * D_];        // x lo split
__device__ __nv_bfloat16 g_wh[(size_t)NC * D_];           // W^T hi  [n][k]
__device__ __nv_bfloat16 g_wl[(size_t)NC * D_];           // W^T lo  [n][k]
__device__ float g_scores[NROWS];
__device__ float g_attn[NROWS];
__device__ float g_part[B_ * 32 * D_];
__device__ float g_h[B_ * D_];
__device__ float g_h1[B_ * M_];
__device__ float g_h2[B_ * M_];

// ---------------------------------------------------------------------------
// Helpers (baseline PTX only: ldmatrix / mma.sync / cp.async — all sm_80+)
// ---------------------------------------------------------------------------
__device__ __forceinline__ uint32_t smem_u32(const void* p) {
    uint32_t a;
    asm("{ .reg .u64 t; cvta.to.shared.u64 t, %1; cvt.u32.u64 %0, t; }"
        : "=r"(a) : "l"(p));
    return a;
}

// Swizzle<1,4,3> for 32-byte rows: bit4 ^= bit7 (conflict-free 8-row ldmatrix)
#define SWZ32(o) ((o) ^ ((((uint32_t)(o)) >> 3) & 0x10u))

__device__ __forceinline__ void cp_async16(uint32_t sdst, const void* gsrc) {
    asm volatile("cp.async.cg.shared.global [%0], [%1], 16;"
                 :: "r"(sdst), "l"(gsrc) : "memory");
}
#define CP_COMMIT() asm volatile("cp.async.commit_group;" ::: "memory")
#define CP_WAIT(n)  asm volatile("cp.async.wait_group %0;" :: "n"(n) : "memory")

__device__ __forceinline__ void ldm_x4(uint32_t* r, uint32_t addr) {
    asm volatile("ldmatrix.sync.aligned.m8n8.x4.shared.b16 {%0,%1,%2,%3}, [%4];"
                 : "=r"(r[0]), "=r"(r[1]), "=r"(r[2]), "=r"(r[3]) : "r"(addr));
}

__device__ __forceinline__ void mma_bf16(float* c, const uint32_t* a, const uint32_t* b) {
    asm volatile(
        "mma.sync.aligned.m16n8k16.row.col.f32.bf16.bf16.f32 "
        "{%0,%1,%2,%3}, {%4,%5,%6,%7}, {%8,%9}, {%0,%1,%2,%3};"
        : "+f"(c[0]), "+f"(c[1]), "+f"(c[2]), "+f"(c[3])
        : "r"(a[0]), "r"(a[1]), "r"(a[2]), "r"(a[3]), "r"(b[0]), "r"(b[1]));
}

// ---------------------------------------------------------------------------
// fp32 -> bf16 hi/lo split conversions
// ---------------------------------------------------------------------------
__global__ void convert_x(const float* __restrict__ x)
{
    const size_t i = (size_t)blockIdx.x * blockDim.x + threadIdx.x;  // float4 idx
    const float4 v = ((const float4*)x)[i];
    __nv_bfloat16 h0 = __float2bfloat16(v.x), h1 = __float2bfloat16(v.y);
    __nv_bfloat16 h2 = __float2bfloat16(v.z), h3 = __float2bfloat16(v.w);
    __nv_bfloat16 l0 = __float2bfloat16(v.x - __bfloat162float(h0));
    __nv_bfloat16 l1 = __float2bfloat16(v.y - __bfloat162float(h1));
    __nv_bfloat16 l2 = __float2bfloat16(v.z - __bfloat162float(h2));
    __nv_bfloat16 l3 = __float2bfloat16(v.w - __bfloat162float(h3));
    ((__nv_bfloat162*)g_xh)[i * 2 + 0] = __halves2bfloat162(h0, h1);
    ((__nv_bfloat162*)g_xh)[i * 2 + 1] = __halves2bfloat162(h2, h3);
    ((__nv_bfloat162*)g_xl)[i * 2 + 0] = __halves2bfloat162(l0, l1);
    ((__nv_bfloat162*)g_xl)[i * 2 + 1] = __halves2bfloat162(l2, l3);
}

__global__ void convert_w(const float* __restrict__ W)
{
    const int e = blockIdx.x * blockDim.x + threadIdx.x;   // < 512*1536
    const int k = e / NC, n = e % NC;
    const float v = W[e];
    __nv_bfloat16 hi = __float2bfloat16(v);
    __nv_bfloat16 lo = __float2bfloat16(v - __bfloat162float(hi));
    g_wh[(size_t)n * D_ + k] = hi;
    g_wl[(size_t)n * D_ + k] = lo;
}

// ---------------------------------------------------------------------------
// QKV GEMM via mma.sync bf16x3:
//   C[65536 x 1536] = x[65536 x 512] @ W[512 x 1536] + b
// CTA tile 128x128, K-chunk 16, cp.async double-buffered, 2 CTAs/SM.
// Pass-structured inner loop (hh -> hl -> lh) keeps frag register
// lifetimes disjoint so __launch_bounds__(256,2) holds without spills.
// ---------------------------------------------------------------------------
constexpr int TM = 128, TN = 128, TK = 16;
constexpr int NCHUNK = D_ / TK;  // 32
// smem: 2 stages x 4 tiles (Ah, Al, Bh, Bl) x 4KB (128 rows x 32B)
constexpr int STAGE_BYTES = 4 * 4096;

__global__ __launch_bounds__(256, 2)
void qkv_mma(const float* __restrict__ bias,
             float* __restrict__ q_out, float* __restrict__ k_out)
{
    __shared__ __align__(128) uint8_t sm[2 * STAGE_BYTES];   // 32 KB
    const uint32_t sb = smem_u32(sm);

    const int tid  = threadIdx.x;
    const int warp = tid >> 5, lane = tid & 31;
    const int n0 = blockIdx.x * TN;
    const int m0 = blockIdx.y * TM;
    const int wm = (warp & 1) * 64;        // warp row offset
    const int wn = (warp >> 1) * 32;       // warp col offset

    // per-thread cp.async coords: one 16B chunk per tile (128 rows x 2 cols)
    const int lr = tid >> 1;               // row 0..127
    const int lc = tid & 1;                // 16B col 0..1
    const uint32_t so = SWZ32(lr * 32 + lc * 16);

    const __nv_bfloat16* xh = g_xh;
    const __nv_bfloat16* xl = g_xl;
    const __nv_bfloat16* wh = g_wh;
    const __nv_bfloat16* wl = g_wl;

    auto load_stage = [&](int stage, int ch) {
        const size_t ga = (size_t)(m0 + lr) * D_ + ch * TK + lc * 8;
        const size_t gb = (size_t)(n0 + lr) * D_ + ch * TK + lc * 8;
        const uint32_t s0 = sb + stage * STAGE_BYTES;
        cp_async16(s0 + 0 * 4096 + so, xh + ga);
        cp_async16(s0 + 1 * 4096 + so, xl + ga);
        cp_async16(s0 + 2 * 4096 + so, wh + gb);
        cp_async16(s0 + 3 * 4096 + so, wl + gb);
    };

    float acc[4][4][4];
    #pragma unroll
    for (int i = 0; i < 4; i++)
        #pragma unroll
        for (int j = 0; j < 4; j++)
            #pragma unroll
            for (int e = 0; e < 4; e++) acc[i][j][e] = 0.f;

    // ldmatrix lane addressing (precomputed; swizzle applied per-fragment)
    const uint32_t a_row = (lane & 15);            // + wm + mf*16
    const uint32_t a_byt = (lane >> 4) << 4;
    const uint32_t b_row = ((lane >> 4) << 3) + (lane & 7);   // + wn + p*16
    const uint32_t b_byt = ((lane >> 3) & 1) << 4;

    load_stage(0, 0);
    CP_COMMIT();

    for (int ch = 0; ch < NCHUNK; ch++) {
        if (ch + 1 < NCHUNK) {
            load_stage((ch + 1) & 1, ch + 1); CP_COMMIT();
            CP_WAIT(1);
        } else {
            CP_WAIT(0);
        }
        __syncthreads();

        const uint32_t s0 = sb + (ch & 1) * STAGE_BYTES;

        uint32_t ra[4], rb[4];
        #pragma unroll
        for (int mf = 0; mf < 4; mf++)
            ra[mf] = SWZ32((uint32_t)(wm + mf * 16 + a_row) * 32 + a_byt);
        #pragma unroll
        for (int p = 0; p < 2; p++)
            rb[p] = SWZ32((uint32_t)(wn + p * 16 + b_row) * 32 + b_byt);

        // --- pass 1: Ah x Bh ---
        uint32_t ah[4][4];
        #pragma unroll
        for (int mf = 0; mf < 4; mf++) ldm_x4(ah[mf], s0 + 0 * 4096 + ra[mf]);
        uint32_t bh[4][2];
        #pragma unroll
        for (int p = 0; p < 2; p++) {
            uint32_t t[4];
            ldm_x4(t, s0 + 2 * 4096 + rb[p]);
            bh[p * 2][0] = t[0]; bh[p * 2][1] = t[1];
            bh[p * 2 + 1][0] = t[2]; bh[p * 2 + 1][1] = t[3];
        }
        #pragma unroll
        for (int mf = 0; mf < 4; mf++)
            #pragma unroll
            for (int nf = 0; nf < 4; nf++) mma_bf16(acc[mf][nf], ah[mf], bh[nf]);

        // --- pass 2: Ah x Bl ---
        {
            uint32_t bl[4][2];
            #pragma unroll
            for (int p = 0; p < 2; p++) {
                uint32_t t[4];
                ldm_x4(t, s0 + 3 * 4096 + rb[p]);
                bl[p * 2][0] = t[0]; bl[p * 2][1] = t[1];
                bl[p * 2 + 1][0] = t[2]; bl[p * 2 + 1][1] = t[3];
            }
            #pragma unroll
            for (int mf = 0; mf < 4; mf++)
                #pragma unroll
                for (int nf = 0; nf < 4; nf++) mma_bf16(acc[mf][nf], ah[mf], bl[nf]);
        }

        // --- pass 3: Al x Bh (reuses bh; ah dead -> regs recycled for al) ---
        {
            uint32_t al[4][4];
            #pragma unroll
            for (int mf = 0; mf < 4; mf++) ldm_x4(al[mf], s0 + 1 * 4096 + ra[mf]);
            #pragma unroll
            for (int mf = 0; mf < 4; mf++)
                #pragma unroll
                for (int nf = 0; nf < 4; nf++) mma_bf16(acc[mf][nf], al[mf], bh[nf]);
        }
        __syncthreads();
    }

    // Epilogue: direct global float2 stores (+bias), route q/k/v per CTA
    const int region = n0 >> 9;                 // 0=q, 1=k, 2=v
    float* dst = (region == 0) ? q_out : (region == 1 ? k_out : (float*)g_v);
    const int cbase = n0 - region * 512;

    #pragma unroll
    for (int mf = 0; mf < 4; mf++) {
        #pragma unroll
        for (int nf = 0; nf < 4; nf++) {
            const int colg = n0 + wn + nf * 8 + (lane & 3) * 2;
            const float2 bv = *(const float2*)(bias + colg);
            const int col = cbase + wn + nf * 8 + (lane & 3) * 2;
            const int r0 = m0 + wm + mf * 16 + (lane >> 2);
            float2 v0 = make_float2(acc[mf][nf][0] + bv.x, acc[mf][nf][1] + bv.y);
            float2 v1 = make_float2(acc[mf][nf][2] + bv.x, acc[mf][nf][3] + bv.y);
            *(float2*)(dst + (size_t)r0 * D_ + col)       = v0;
            *(float2*)(dst + (size_t)(r0 + 8) * D_ + col) = v1;
        }
    }
}

// ---------------------------------------------------------------------------
// scores[b,s] = q_last[b,:] . k[b,s,:]    (one warp per (b,s))
// ---------------------------------------------------------------------------
__global__ void scores_kernel(const float* __restrict__ q, const float* __restrict__ k)
{
    const int gw   = (blockIdx.x * blockDim.x + threadIdx.x) >> 5;
    const int lane = threadIdx.x & 31;
    const int b    = gw >> 12;

    const float4* qr = (const float4*)(q + ((size_t)b * S_ + (S_ - 1)) * D_);
    const float4* kr = (const float4*)(k + (size_t)gw * D_);

    float acc = 0.f;
    #pragma unroll
    for (int it = 0; it < 4; it++) {
        float4 qv = qr[lane + it * 32];
        float4 kv = kr[lane + it * 32];
        acc += qv.x * kv.x + qv.y * kv.y + qv.z * kv.z + qv.w * kv.w;
    }
    #pragma unroll
    for (int off = 16; off; off >>= 1) acc += __shfl_xor_sync(0xffffffffu, acc, off);
    if (lane == 0) g_scores[gw] = acc;
}

__global__ void softmax_kernel()
{
    __shared__ float red[512];
    const int b = blockIdx.x, tid = threadIdx.x;
    const float* sc = g_scores + (size_t)b * S_;

    float lm = -1e30f;
    for (int i = tid; i < S_; i += 512) lm = fmaxf(lm, sc[i]);
    red[tid] = lm; __syncthreads();
    for (int s = 256; s; s >>= 1) {
        if (tid < s) red[tid] = fmaxf(red[tid], red[tid + s]);
        __syncthreads();
    }
    const float mx = red[0];
    __syncthreads();

    float ls = 0.f;
    for (int i = tid; i < S_; i += 512) {
        float e = expf(sc[i] - mx);
        g_attn[(size_t)b * S_ + i] = e;
        ls += e;
    }
    red[tid] = ls; __syncthreads();
    for (int s = 256; s; s >>= 1) {
        if (tid < s) red[tid] += red[tid + s];
        __syncthreads();
    }
    const float inv = 1.f / red[0];
    for (int i = tid; i < S_; i += 512) g_attn[(size_t)b * S_ + i] *= inv;
}

// ---------------------------------------------------------------------------
// sa_last partials: block (b, chunk) accumulates 128 s-rows of attn*v,
// two independent accumulators for ILP.
// ---------------------------------------------------------------------------
__global__ void sa_part_kernel()
{
    const int b = blockIdx.x, ch = blockIdx.y, d = threadIdx.x;
    const float* vp = g_v + ((size_t)b * S_ + ch * 128) * D_ + d;
    const float* ap = g_attn + (size_t)b * S_ + ch * 128;
    float a0 = 0.f, a1 = 0.f;
    #pragma unroll 8
    for (int s = 0; s < 128; s += 2) {
        a0 = fmaf(ap[s],     vp[(size_t)s * D_],        a0);
        a1 = fmaf(ap[s + 1], vp[(size_t)(s + 1) * D_],  a1);
    }
    g_part[(b * 32 + ch) * D_ + d] = a0 + a1;
}

// h[b,d] = x[b, S-1, d] + sum_ch part[b,ch,d]
__global__ void sa_reduce_kernel(const float* __restrict__ x)
{
    const int b = blockIdx.x, d = threadIdx.x;
    float acc = x[((size_t)b * S_ + (S_ - 1)) * D_ + d];
    #pragma unroll
    for (int ch = 0; ch < 32; ch++) acc += g_part[(b * 32 + ch) * D_ + d];
    g_h[b * D_ + d] = acc;
}

__global__ __launch_bounds__(256)
void mlp1_kernel(const float* __restrict__ W1, const float* __restrict__ b1)
{
    __shared__ float hs[D_];
    const int b = blockIdx.x, tid = threadIdx.x;
    hs[tid]       = g_h[b * D_ + tid];
    hs[tid + 256] = g_h[b * D_ + tid + 256];
    __syncthreads();
    const int m = blockIdx.y * 256 + tid;
    float acc = b1[m];
    #pragma unroll 8
    for (int k = 0; k < D_; k++) acc = fmaf(hs[k], W1[(size_t)k * M_ + m], acc);
    g_h1[b * M_ + m] = fmaxf(acc, 0.f);
}

__global__ __launch_bounds__(256)
void mlp2_kernel(const float* __restrict__ W2, const float* __restrict__ b2)
{
    __shared__ float hs[M_];
    const int b = blockIdx.x, tid = threadIdx.x;
    for (int i = tid; i < M_; i += 256) hs[i] = g_h1[b * M_ + i];
    __syncthreads();
    const int m = blockIdx.y * 256 + tid;
    float acc = b2[m];
    #pragma unroll 8
    for (int k = 0; k < M_; k++) acc = fmaf(hs[k], W2[(size_t)k * M_ + m], acc);
    g_h2[b * M_ + m] = fmaxf(acc, 0.f);
}

__global__ void mlp3_kernel(const float* __restrict__ W3, const float* __restrict__ b3,
                            float* __restrict__ out)
{
    const int w = threadIdx.x >> 5, lane = threadIdx.x & 31;
    float acc = 0.f;
    #pragma unroll
    for (int i = 0; i < M_ / 32; i++)
        acc = fmaf(g_h2[w * M_ + lane + i * 32], W3[lane + i * 32], acc);
    #pragma unroll
    for (int off = 16; off; off >>= 1) acc += __shfl_xor_sync(0xffffffffu, acc, off);
    if (lane == 0) out[w] = acc + b3[0];
}

// ---------------------------------------------------------------------------
// Entry. Output layout: (out, q, k) flat: [0,16) out, then q, then k.
// ---------------------------------------------------------------------------
extern "C" void kernel_launch(void* const* d_in, const int* in_sizes, int n_in,
                              void* d_out, int out_size)
{
    const float* x     = (const float*)d_in[0];
    const float* W_qkv = (const float*)d_in[1];
    const float* b_qkv = (const float*)d_in[2];
    const float* W1    = (const float*)d_in[3];
    const float* b1    = (const float*)d_in[4];
    const float* W2    = (const float*)d_in[5];
    const float* b2    = (const float*)d_in[6];
    const float* W3    = (const float*)d_in[7];
    const float* b3    = (const float*)d_in[8];

    float* out   = (float*)d_out;
    float* q_out = out + 16;
    float* k_out = out + 16 + (size_t)NROWS * D_;

    convert_x<<<(NROWS * D_ / 4) / 256, 256>>>(x);
    convert_w<<<(D_ * NC) / 256, 256>>>(W_qkv);
    qkv_mma<<<dim3(NC / TN, NROWS / TM), 256>>>(b_qkv, q_out, k_out);
    scores_kernel<<<NROWS / 8, 256>>>(q_out, k_out);
    softmax_kernel<<<B_, 512>>>();
    sa_part_kernel<<<dim3(B_, 32), 512>>>();
    sa_reduce_kernel<<<B_, D_>>>(x);
    mlp1_kernel<<<dim3(B_, M_ / 256), 256>>>(W1, b1);
    mlp2_kernel<<<dim3(B_, M_ / 256), 256>>>(W2, b2);
    mlp3_kernel<<<1, 512>>>(W3, b3, out);
}